// round 6
// baseline (speedup 1.0000x reference)
#include <cuda_runtime.h>

// Problem constants
#define BB     32
#define CC     16
#define IN_H   64
#define IN_W   64
#define OUT_H  60
#define OUT_W  60
#define KK     5
#define JT     12              // output cols per block
#define XCOLS  16              // JT + KK - 1
#define XSTR   36              // padded batch stride (32 + 4), 144B = 16B aligned
#define NTHREADS 192           // 6 warps, 2 pixels/warp -> 12 pixels

// Scratch: transposed input inT[c][y][x][b]  (batch contiguous)
__device__ float g_inT[CC * IN_H * IN_W * BB];

// ---------------------------------------------------------------------------
// Pre-kernel: in[b][c][y][x] -> inT[c][y][x][b]   (8.4MB read + 8.4MB write)
// ---------------------------------------------------------------------------
__global__ void transpose_kernel(const float* __restrict__ in) {
    __shared__ float s[IN_W][BB + 1];   // +1 pad: conflict-free both phases
    const int c = blockIdx.x;
    const int y = blockIdx.y;
    const int t = threadIdx.x;          // 256 threads

    // coalesced load: lanes sweep x
    #pragma unroll
    for (int it = 0; it < 8; ++it) {
        int n = t + it * 256;           // 0..2047
        int x = n & 63;
        int b = n >> 6;
        s[x][b] = in[((b * CC + c) * IN_H + y) * IN_W + x];
    }
    __syncthreads();

    // coalesced store: lanes sweep b
    float* dst = g_inT + (size_t)(c * IN_H + y) * IN_W * BB;
    #pragma unroll
    for (int it = 0; it < 8; ++it) {
        int n = t + it * 256;
        int b = n & 31;
        int x = n >> 5;
        dst[x * BB + b] = s[x][b];
    }
}

// ---------------------------------------------------------------------------
// f32x2 helpers (FFMA2 is reachable only via PTX fma.rn.f32x2)
// ---------------------------------------------------------------------------
__device__ __forceinline__ unsigned long long ffma2(
    unsigned long long a, unsigned long long b, unsigned long long c) {
    unsigned long long d;
    asm("fma.rn.f32x2 %0, %1, %2, %3;" : "=l"(d) : "l"(a), "l"(b), "l"(c));
    return d;
}
__device__ __forceinline__ unsigned long long pack2(float x, float y) {
    unsigned long long r;
    asm("mov.b64 %0, {%1, %2};" : "=l"(r) : "f"(x), "f"(y));
    return r;
}
__device__ __forceinline__ void unpack2(unsigned long long v, float& x, float& y) {
    asm("mov.b64 {%0, %1}, %2;" : "=f"(x), "=f"(y) : "l"(v));
}

// ---------------------------------------------------------------------------
// Main kernel.
//   block  = (j-tile, i-row), grid (5, 60)
//   warp   = 2 output pixels; lane: pix = lane>>4, bh = (lane>>3)&1, kop = lane&7
//   thread = k_out pair {2*kop, 2*kop+1} x 16 batches (bh half) x 1 pixel
// Per (c,u,v) step: 1 LDG.64 weight, 4 LDS.128 input, 16 FFMA2.
// ---------------------------------------------------------------------------
__global__ __launch_bounds__(NTHREADS)
void lc_kernel(const float* __restrict__ wgt, float* __restrict__ out) {
    __shared__ float s[2][KK * XCOLS * XSTR];   // double buffered channel tile

    const int j0   = blockIdx.x * JT;
    const int i    = blockIdx.y;
    const int tid  = threadIdx.x;
    const int warp = tid >> 5;
    const int lane = tid & 31;
    const int pix  = lane >> 4;
    const int bh   = (lane >> 3) & 1;
    const int kop  = lane & 7;
    const int jl   = warp * 2 + pix;            // 0..11
    const int j    = j0 + jl;

    // weight pointer as float2, for k_out pair (2*kop, 2*kop+1)
    // element index (floats) = ((i*60 + j)*6400) + uv-major strides + 2*kop
    const float2* wpc = (const float2*)wgt + (size_t)(i * OUT_W + j) * 3200 + kop;

    unsigned long long acc0[8], acc1[8];
    #pragma unroll
    for (int r = 0; r < 8; ++r) { acc0[r] = 0ull; acc1[r] = 0ull; }

    // ---- prologue: stage channel 0 ----
    // 640 float4 tiles: n -> bq = n&7, x = (n>>3)&15, y = n>>7
    {
        #pragma unroll
        for (int it = 0; it < 4; ++it) {
            int n = tid + it * NTHREADS;
            if (n < 640) {
                int bq = n & 7, x = (n >> 3) & 15, y = n >> 7;
                float4 v = *(const float4*)&g_inT[
                    ((size_t)(0 * IN_H + i + y) * IN_W + (j0 + x)) * BB + 4 * bq];
                *(float4*)&s[0][(y * XCOLS + x) * XSTR + 4 * bq] = v;
            }
        }
    }
    __syncthreads();

    int cur = 0;
    for (int c = 0; c < CC; ++c) {
        // ---- prefetch next channel into registers (overlaps compute) ----
        float4 pf[4];
        if (c + 1 < CC) {
            #pragma unroll
            for (int it = 0; it < 4; ++it) {
                int n = tid + it * NTHREADS;
                if (n < 640) {
                    int bq = n & 7, x = (n >> 3) & 15, y = n >> 7;
                    pf[it] = *(const float4*)&g_inT[
                        ((size_t)((c + 1) * IN_H + i + y) * IN_W + (j0 + x)) * BB + 4 * bq];
                }
            }
        }

        // ---- compute on current buffer ----
        const float* sb = s[cur];
        #pragma unroll
        for (int u = 0; u < KK; ++u) {
            float2 wv[KK];
            #pragma unroll
            for (int v = 0; v < KK; ++v)
                wv[v] = wpc[(u * KK + v) * 8];
            #pragma unroll
            for (int v = 0; v < KK; ++v) {
                const float4* ip = (const float4*)(
                    sb + (u * XCOLS + jl + v) * XSTR + bh * 16);
                const unsigned long long w0 = pack2(wv[v].x, wv[v].x);
                const unsigned long long w1 = pack2(wv[v].y, wv[v].y);
                #pragma unroll
                for (int q = 0; q < 4; ++q) {
                    float4 xv = ip[q];
                    unsigned long long lo = pack2(xv.x, xv.y);
                    unsigned long long hi = pack2(xv.z, xv.w);
                    acc0[2 * q]     = ffma2(lo, w0, acc0[2 * q]);
                    acc0[2 * q + 1] = ffma2(hi, w0, acc0[2 * q + 1]);
                    acc1[2 * q]     = ffma2(lo, w1, acc1[2 * q]);
                    acc1[2 * q + 1] = ffma2(hi, w1, acc1[2 * q + 1]);
                }
            }
        }

        // ---- drain prefetch into the other buffer ----
        if (c + 1 < CC) {
            #pragma unroll
            for (int it = 0; it < 4; ++it) {
                int n = tid + it * NTHREADS;
                if (n < 640) {
                    int bq = n & 7, x = (n >> 3) & 15, y = n >> 7;
                    *(float4*)&s[cur ^ 1][(y * XCOLS + x) * XSTR + 4 * bq] = pf[it];
                }
            }
        }
        __syncthreads();
        cur ^= 1;
        wpc += 25 * 8;   // next channel (400 floats = 200 float2)
    }

    // ---- epilogue: out[b][ko][i][j] ----
    #pragma unroll
    for (int p = 0; p < 8; ++p) {
        float a0, a1, b0v, b1v;
        unpack2(acc0[p], a0, a1);   // ko = 2*kop,   batches bh*16+2p, +1
        unpack2(acc1[p], b0v, b1v); // ko = 2*kop+1
        int bA = bh * 16 + 2 * p;
        int ko0 = 2 * kop;
        size_t baseA = ((size_t)(bA * CC + ko0) * OUT_H + i) * OUT_W + j;
        size_t baseB = ((size_t)((bA + 1) * CC + ko0) * OUT_H + i) * OUT_W + j;
        out[baseA]                         = a0;
        out[baseA + (size_t)OUT_H * OUT_W] = b0v;
        out[baseB]                         = a1;
        out[baseB + (size_t)OUT_H * OUT_W] = b1v;
    }
}

// ---------------------------------------------------------------------------
extern "C" void kernel_launch(void* const* d_in, const int* in_sizes, int n_in,
                              void* d_out, int out_size) {
    const float* in_spikes = (const float*)d_in[0];
    const float* weights   = (const float*)d_in[1];
    float* out             = (float*)d_out;

    transpose_kernel<<<dim3(CC, IN_H), 256>>>(in_spikes);
    lc_kernel<<<dim3(OUT_W / JT, OUT_H), NTHREADS>>>(weights, out);
}